// round 11
// baseline (speedup 1.0000x reference)
#include <cuda_runtime.h>

// x: [32, 256, 64, 64] f32; weight: [256, 256, 3, 3] f32; bias: [256] f32
// out: [32, 256, 1, 1] f32   (spatial = 128*128 = 16384)
#define B_   32
#define C_   256
#define O_   256
#define HW_  4096            // 64*64
#define BC_  (B_ * C_)       // 8192 stats (producer) blocks

// Consumer tiling: block = (o-tile of 8) x (channel-tile of 16)
#define OT_  8
#define QC_  16
#define NOT_ (O_ / OT_)      // 32
#define NQ_  (C_ / QC_)      // 16
#define NCONS (NOT_ * NQ_)   // 512 consumer blocks
#define NPROD BC_            // 8192 producers
#define NTOTAL (NPROD + NCONS)

// Scratch (no allocations). Counters zero-init at load; every launch resets
// them itself (replay-safe; pattern validated in R4/R8/R9).
__device__ float g_statsT[C_][B_][4];         // [c][b] -> (T, R0, C0, x00)
__device__ float g_part[NOT_][NQ_][OT_][B_];  // partial sums
__device__ unsigned int g_done[NOT_ * 32];    // per-o-tile election ctr (padded)
__device__ unsigned int g_cnt;                // producers completed
__device__ unsigned int g_cnt2;               // consumers past barrier

// release-increment: orders prior global stores, emits NO CCTL.IVALL
__device__ __forceinline__ void release_count(unsigned int* p) {
    asm volatile("red.release.gpu.add.u32 [%0], %1;" :: "l"(p), "r"(1u) : "memory");
}
__device__ __forceinline__ unsigned int acquire_load(const unsigned int* p) {
    unsigned int v;
    asm volatile("ld.acquire.gpu.u32 %0, [%1];" : "=r"(v) : "l"(p) : "memory");
    return v;
}
// acq_rel fetch-add: release own prior stores + acquire others' (no CCTL)
__device__ __forceinline__ unsigned int acqrel_add(unsigned int* p) {
    unsigned int v;
    asm volatile("atom.acq_rel.gpu.add.u32 %0, [%1], %2;"
                 : "=r"(v) : "l"(p), "r"(1u) : "memory");
    return v;
}

// ---------------------------------------------------------------------------
// Single fused launch. __launch_bounds__(256, 8) forces <=32 regs so the
// streaming phase keeps 8 blocks/SM (R9 regression root-cause: 40 regs ->
// 6 blocks/SM -> DRAM 54%).
//   blocks [0, 8192)    : per-(b,c) image stats — 134 MB roofline stream
//   blocks [8192, 8704) : consumers — fold weights pre-barrier, backoff spin,
//                         16-channel partial dot, acq_rel election, epilogue
// ---------------------------------------------------------------------------
__global__ void __launch_bounds__(256, 8) fused_kernel(const float* __restrict__ x,
                                                       const float* __restrict__ w,
                                                       const float* __restrict__ bias,
                                                       float* __restrict__ out) {
    const int t = threadIdx.x;

    if (blockIdx.x < NPROD) {
        // ================= stats producer =================
        const int bc = blockIdx.x;
        const float4* __restrict__ p4 =
            reinterpret_cast<const float4*>(x + (size_t)bc * HW_);

        float s = 0.f, r0 = 0.f, c0 = 0.f, v00 = 0.f;

        #pragma unroll
        for (int i = 0; i < 4; i++) {
            const int j = t + i * 256;        // float4 index 0..1023
            float4 v = __ldcs(&p4[j]);        // streaming, read-once
            float vs = v.x + v.y + v.z + v.w;
            s += vs;
            if (j < 16)          r0 += vs;    // row 0 = first 64 elems
            if ((j & 15) == 0)   c0 += v.x;   // col 0 = elem % 64 == 0
            if (j == 0)          v00 = v.x;
        }

        #pragma unroll
        for (int off = 16; off > 0; off >>= 1) {
            s  += __shfl_xor_sync(0xFFFFFFFFu, s,  off);
            r0 += __shfl_xor_sync(0xFFFFFFFFu, r0, off);
            c0 += __shfl_xor_sync(0xFFFFFFFFu, c0, off);
        }

        __shared__ float ss[8], sr[8], sc[8];
        __shared__ float sv00;
        const int warp = t >> 5, lane = t & 31;
        if (t == 0) sv00 = v00;
        if (lane == 0) { ss[warp] = s; sr[warp] = r0; sc[warp] = c0; }
        __syncthreads();

        if (warp == 0) {
            float fs = (lane < 8) ? ss[lane] : 0.f;
            float fr = (lane < 8) ? sr[lane] : 0.f;
            float fc = (lane < 8) ? sc[lane] : 0.f;
            #pragma unroll
            for (int off = 4; off > 0; off >>= 1) {
                fs += __shfl_xor_sync(0xFFFFFFFFu, fs, off);
                fr += __shfl_xor_sync(0xFFFFFFFFu, fr, off);
                fc += __shfl_xor_sync(0xFFFFFFFFu, fc, off);
            }
            if (lane == 0) {
                const int b = bc >> 8;
                const int c = bc & 255;
                *reinterpret_cast<float4*>(&g_statsT[c][b][0]) =
                    make_float4(fs, fr, fc, sv00);
                release_count(&g_cnt);        // release, no L1 flush
            }
        }
    } else {
        // ================= consumer =================
        const int ci = blockIdx.x - NPROD;
        const int ot = ci >> 4;               // / NQ_
        const int q  = ci & (NQ_ - 1);
        const int obase = ot * OT_;
        const int cbase = q * QC_;

        __shared__ float4 wsm[QC_ * OT_];     // [c_local][o_local]
        __shared__ unsigned int s_old;

        // ---- fold weights BEFORE waiting (independent of stats) ----
        if (t < QC_ * OT_) {
            const int c_l = t >> 3;
            const int o_l = t & (OT_ - 1);
            const float* p = w + ((size_t)(cbase + c_l) * O_ + (obase + o_l)) * 9;
            float w00 = __ldg(p + 0), w01 = __ldg(p + 1), w02 = __ldg(p + 2);
            float w10 = __ldg(p + 3), w11 = __ldg(p + 4), w12 = __ldg(p + 5);
            float w20 = __ldg(p + 6), w21 = __ldg(p + 7), w22 = __ldg(p + 8);
            float wsum = ((w00 + w01) + (w02 + w10)) + ((w11 + w12) + (w20 + w21)) + w22;
            float wkh0 = w00 + w01 + w02;     // kh == 0 row
            float wkw0 = w00 + w10 + w20;     // kw == 0 col
            wsm[t] = make_float4(wsum, -wkh0, -wkw0, w00);
        }
        __syncthreads();

        // ---- spin-wait for all producers (long backoff) ----
        if (t == 0) {
            if (acquire_load(&g_cnt) < (unsigned int)NPROD) {
                do { __nanosleep(1024); }
                while (acquire_load(&g_cnt) < (unsigned int)NPROD);
            }
        }
        __syncthreads();

        // replay-safe reset of the producer counter (after ALL consumers pass)
        if (t == 0) {
            unsigned int old = atomicAdd(&g_cnt2, 1u);
            if (old == (unsigned int)NCONS - 1u) {
                atomicExch(&g_cnt, 0u);
                atomicExch(&g_cnt2, 0u);
            }
        }

        // ---- 16-channel partial dot: warp = local o, lane = batch ----
        const int o_l = t >> 5;
        const int b   = t & 31;

        float acc0 = 0.f, acc1 = 0.f;
        #pragma unroll
        for (int k = 0; k < QC_; k += 2) {
            const float4 a0 = __ldcg(reinterpret_cast<const float4*>(&g_statsT[cbase + k][b][0]));
            const float4 w0 = wsm[k * OT_ + o_l];
            const float4 a1 = __ldcg(reinterpret_cast<const float4*>(&g_statsT[cbase + k + 1][b][0]));
            const float4 w1 = wsm[(k + 1) * OT_ + o_l];
            acc0 = fmaf(a0.x, w0.x, acc0);
            acc1 = fmaf(a1.x, w1.x, acc1);
            acc0 = fmaf(a0.y, w0.y, acc0);
            acc1 = fmaf(a1.y, w1.y, acc1);
            acc0 = fmaf(a0.z, w0.z, acc0);
            acc1 = fmaf(a1.z, w1.z, acc1);
            acc0 = fmaf(a0.w, w0.w, acc0);
            acc1 = fmaf(a1.w, w1.w, acc1);
        }
        // plain store; ordered before the acq_rel election add below
        g_part[ot][q][o_l][b] = acc0 + acc1;  // coalesced 128 B per warp

        // ---- election: last block per o-tile combines (acq_rel, no CCTL) ----
        __syncthreads();
        if (t == 0) s_old = acqrel_add(&g_done[ot * 32]);
        __syncthreads();

        if (s_old == (unsigned int)NQ_ - 1u) {
            float sacc = 0.f;
            #pragma unroll
            for (int qq = 0; qq < NQ_; qq++)  // fixed order -> deterministic
                sacc += __ldcg(&g_part[ot][qq][o_l][b]);
            const int o = obase + o_l;
            out[b * O_ + o] = 2.0f * (sacc * (1.0f / 16384.0f) + __ldg(&bias[o]));
            if (t == 0) atomicExch(&g_done[ot * 32], 0u);   // replay-safe
        }
    }
}

// ---------------------------------------------------------------------------
extern "C" void kernel_launch(void* const* d_in, const int* in_sizes, int n_in,
                              void* d_out, int out_size) {
    const float* x    = (const float*)d_in[0];
    const float* wgt  = (const float*)d_in[1];
    const float* bias = (const float*)d_in[2];
    float* out        = (float*)d_out;

    fused_kernel<<<NTOTAL, 256>>>(x, wgt, bias, out);
}

// round 12
// speedup vs baseline: 1.0640x; 1.0640x over previous
#include <cuda_runtime.h>

// x: [32, 256, 64, 64] f32; weight: [256, 256, 3, 3] f32; bias: [256] f32
// out: [32, 256, 1, 1] f32   (spatial = 128*128 = 16384)
#define B_   32
#define C_   256
#define O_   256
#define HW_  4096            // 64*64
#define BC_  (B_ * C_)       // 8192
#define CO_  (C_ * O_)       // 65536
#define WPREP_BLOCKS (CO_ / 256)   // 256

// Kernel-B tiling: block = (8 o's) x (32 channels)
#define OT_  8
#define QC_  32
#define NOT_ (O_ / OT_)      // 32 o-tiles
#define NQ_  (C_ / QC_)      // 8 channel-tiles
// grid B = NOT_ * NQ_ = 256 blocks

// Scratch (no allocations). g_done zero-init at load; reset each launch.
__device__ float4 g_statsT[BC_];              // [c][b] -> (T, R0, C0, x00)
__device__ float4 g_wcatT[CO_];               // [o][c] -> (Wsum,-Wkh0,-Wkw0,W00)
__device__ float  g_part[NOT_][NQ_][OT_][B_]; // partial sums
__device__ unsigned int g_done[NOT_ * 32];    // per-o-tile ctr, line-padded

// acq_rel fetch-add: releases prior stores, acquires others'; NO CCTL.IVALL
__device__ __forceinline__ unsigned int acqrel_add(unsigned int* p) {
    unsigned int v;
    asm volatile("atom.acq_rel.gpu.add.u32 %0, [%1], %2;"
                 : "=r"(v) : "l"(p), "r"(1u) : "memory");
    return v;
}

// ---------------------------------------------------------------------------
// Kernel A (UNCHANGED from R6 — fastest measured config):
// blocks [0,8192): per-(b,c) stats, one 16 KB image each (__ldcs stream);
// blocks [8192,8448): weight folding -> g_wcatT.
// ---------------------------------------------------------------------------
__global__ void __launch_bounds__(256) fused_prep_kernel(const float* __restrict__ x,
                                                         const float* __restrict__ w) {
    if (blockIdx.x < BC_) {
        const int bc = blockIdx.x;
        const float4* __restrict__ p4 =
            reinterpret_cast<const float4*>(x + (size_t)bc * HW_);
        const int t = threadIdx.x;

        float s = 0.f, r0 = 0.f, c0 = 0.f, v00 = 0.f;

        #pragma unroll
        for (int i = 0; i < 4; i++) {
            const int j = t + i * 256;        // float4 index 0..1023
            float4 v = __ldcs(&p4[j]);
            float vs = v.x + v.y + v.z + v.w;
            s += vs;
            if (j < 16)          r0 += vs;    // row 0 = first 64 elems
            if ((j & 15) == 0)   c0 += v.x;   // col 0 = elem % 64 == 0
            if (j == 0)          v00 = v.x;
        }

        #pragma unroll
        for (int off = 16; off > 0; off >>= 1) {
            s  += __shfl_xor_sync(0xFFFFFFFFu, s,  off);
            r0 += __shfl_xor_sync(0xFFFFFFFFu, r0, off);
            c0 += __shfl_xor_sync(0xFFFFFFFFu, c0, off);
        }

        __shared__ float ss[8], sr[8], sc[8];
        __shared__ float sv00;
        const int warp = t >> 5, lane = t & 31;
        if (t == 0) sv00 = v00;
        if (lane == 0) { ss[warp] = s; sr[warp] = r0; sc[warp] = c0; }
        __syncthreads();

        if (warp == 0) {
            float fs = (lane < 8) ? ss[lane] : 0.f;
            float fr = (lane < 8) ? sr[lane] : 0.f;
            float fc = (lane < 8) ? sc[lane] : 0.f;
            #pragma unroll
            for (int off = 4; off > 0; off >>= 1) {
                fs += __shfl_xor_sync(0xFFFFFFFFu, fs, off);
                fr += __shfl_xor_sync(0xFFFFFFFFu, fr, off);
                fc += __shfl_xor_sync(0xFFFFFFFFu, fc, off);
            }
            if (lane == 0) {
                const int b = bc >> 8;
                const int c = bc & 255;
                g_statsT[c * B_ + b] = make_float4(fs, fr, fc, sv00);
            }
        }
    } else {
        const int i = (blockIdx.x - BC_) * 256 + threadIdx.x;   // i = c*256 + o
        const int c = i >> 8;
        const int o = i & 255;
        const float* p = w + (size_t)i * 9;
        float w00 = p[0], w01 = p[1], w02 = p[2];
        float w10 = p[3], w11 = p[4], w12 = p[5];
        float w20 = p[6], w21 = p[7], w22 = p[8];
        float wsum = ((w00 + w01) + (w02 + w10)) + ((w11 + w12) + (w20 + w21)) + w22;
        float wkh0 = w00 + w01 + w02;   // kh == 0 row
        float wkw0 = w00 + w10 + w20;   // kw == 0 col
        g_wcatT[o * C_ + c] = make_float4(wsum, -wkh0, -wkw0, w00);
    }
}

// ---------------------------------------------------------------------------
// Kernel B: o-tiled micro-GEMM over pre-folded weights.
// grid = (o-tile, q) = 32*8 = 256 blocks, 256 threads.
//   phase 0: wsm[o_l][c_l] <- g_wcatT, coalesced 512 B per warp (L2-hot)
//   phase 1: warp = o_l, lane = b; 32-channel dot4. Stats loads are
//            coalesced in b and IDENTICAL across the 8 warps -> L1 reuse.
//            Total stats traffic = 32 o-tiles x 128 KB = 4 MB (was 32 MB).
//   phase 2: partial -> g_part, acq_rel election, last block per o-tile
//            combines 8 partials in fixed order + epilogue.
// ---------------------------------------------------------------------------
__global__ void __launch_bounds__(256) gemm_kernel(const float* __restrict__ bias,
                                                   float* __restrict__ out) {
    const int ot = blockIdx.x >> 3;        // / NQ_
    const int q  = blockIdx.x & (NQ_ - 1);
    const int t  = threadIdx.x;
    const int obase = ot * OT_;
    const int cbase = q * QC_;

    const int o_l = t >> 5;                // warp = local o
    const int b   = t & 31;                // lane = batch

    __shared__ float4 wsm[OT_][QC_];
    __shared__ unsigned int s_old;

    // phase 0: each warp loads its o's 32 folded-weight vectors (coalesced)
    wsm[o_l][b] = g_wcatT[(obase + o_l) * C_ + cbase + b];
    __syncthreads();

    // phase 1: 32-channel partial dot, dual accumulators
    float acc0 = 0.f, acc1 = 0.f;
    #pragma unroll
    for (int k = 0; k < QC_; k += 2) {
        const float4 a0 = g_statsT[(cbase + k) * B_ + b];
        const float4 w0 = wsm[o_l][k];
        const float4 a1 = g_statsT[(cbase + k + 1) * B_ + b];
        const float4 w1 = wsm[o_l][k + 1];
        acc0 = fmaf(a0.x, w0.x, acc0);
        acc1 = fmaf(a1.x, w1.x, acc1);
        acc0 = fmaf(a0.y, w0.y, acc0);
        acc1 = fmaf(a1.y, w1.y, acc1);
        acc0 = fmaf(a0.z, w0.z, acc0);
        acc1 = fmaf(a1.z, w1.z, acc1);
        acc0 = fmaf(a0.w, w0.w, acc0);
        acc1 = fmaf(a1.w, w1.w, acc1);
    }
    g_part[ot][q][o_l][b] = acc0 + acc1;   // coalesced 128 B per warp

    // phase 2: election (acq_rel: no CCTL, orders the partial stores)
    __syncthreads();
    if (t == 0) s_old = acqrel_add(&g_done[ot * 32]);
    __syncthreads();

    if (s_old == (unsigned int)NQ_ - 1u) { // last block for this o-tile
        float sacc = 0.f;
        #pragma unroll
        for (int qq = 0; qq < NQ_; qq++)   // fixed order -> deterministic
            sacc += __ldcg(&g_part[ot][qq][o_l][b]);
        const int o = obase + o_l;
        out[b * O_ + o] = 2.0f * (sacc * (1.0f / 16384.0f) + __ldg(&bias[o]));
        if (t == 0) atomicExch(&g_done[ot * 32], 0u);   // replay-safe reset
    }
}

// ---------------------------------------------------------------------------
extern "C" void kernel_launch(void* const* d_in, const int* in_sizes, int n_in,
                              void* d_out, int out_size) {
    const float* x    = (const float*)d_in[0];
    const float* wgt  = (const float*)d_in[1];
    const float* bias = (const float*)d_in[2];
    float* out        = (float*)d_out;

    fused_prep_kernel<<<BC_ + WPREP_BLOCKS, 256>>>(x, wgt);
    gemm_kernel<<<NOT_ * NQ_, 256>>>(bias, out);
}

// round 13
// speedup vs baseline: 1.0761x; 1.0113x over previous
#include <cuda_runtime.h>

// x: [32, 256, 64, 64] f32; weight: [256, 256, 3, 3] f32; bias: [256] f32
// out: [32, 256, 1, 1] f32   (spatial = 128*128 = 16384)
#define B_   32
#define C_   256
#define O_   256
#define HW_  4096            // 64*64
#define BC_  (B_ * C_)       // 8192
#define CO_  (C_ * O_)       // 65536
#define WPREP_BLOCKS (CO_ / 256)   // 256

// Kernel-B tiling: block = (8 o's) x (16 channels), grid = 32*16 = 512
#define OT_  8
#define QC_  16
#define NOT_ (O_ / OT_)      // 32 o-tiles
#define NQ_  (C_ / QC_)      // 16 channel-tiles

// Scratch (no allocations). g_done zero-init at load; reset each launch.
__device__ float4 g_statsT[BC_];              // [c][b] -> (T, R0, C0, x00)
__device__ float4 g_wcatT[CO_];               // [o][c] -> (Wsum,-Wkh0,-Wkw0,W00)
__device__ float  g_part[NOT_][NQ_][OT_][B_]; // partial sums
__device__ unsigned int g_done[NOT_ * 32];    // per-o-tile ctr, line-padded

// acq_rel fetch-add: releases prior stores, acquires others'; NO CCTL.IVALL
__device__ __forceinline__ unsigned int acqrel_add(unsigned int* p) {
    unsigned int v;
    asm volatile("atom.acq_rel.gpu.add.u32 %0, [%1], %2;"
                 : "=r"(v) : "l"(p), "r"(1u) : "memory");
    return v;
}

// ---------------------------------------------------------------------------
// Kernel A (UNCHANGED — fastest measured config, ~21 us @ 74% DRAM):
// blocks [0,8192): per-(b,c) stats, one 16 KB image each (__ldcs stream);
// blocks [8192,8448): weight folding -> g_wcatT.
// ---------------------------------------------------------------------------
__global__ void __launch_bounds__(256) fused_prep_kernel(const float* __restrict__ x,
                                                         const float* __restrict__ w) {
    if (blockIdx.x < BC_) {
        const int bc = blockIdx.x;
        const float4* __restrict__ p4 =
            reinterpret_cast<const float4*>(x + (size_t)bc * HW_);
        const int t = threadIdx.x;

        float s = 0.f, r0 = 0.f, c0 = 0.f, v00 = 0.f;

        #pragma unroll
        for (int i = 0; i < 4; i++) {
            const int j = t + i * 256;        // float4 index 0..1023
            float4 v = __ldcs(&p4[j]);
            float vs = v.x + v.y + v.z + v.w;
            s += vs;
            if (j < 16)          r0 += vs;    // row 0 = first 64 elems
            if ((j & 15) == 0)   c0 += v.x;   // col 0 = elem % 64 == 0
            if (j == 0)          v00 = v.x;
        }

        #pragma unroll
        for (int off = 16; off > 0; off >>= 1) {
            s  += __shfl_xor_sync(0xFFFFFFFFu, s,  off);
            r0 += __shfl_xor_sync(0xFFFFFFFFu, r0, off);
            c0 += __shfl_xor_sync(0xFFFFFFFFu, c0, off);
        }

        __shared__ float ss[8], sr[8], sc[8];
        __shared__ float sv00;
        const int warp = t >> 5, lane = t & 31;
        if (t == 0) sv00 = v00;
        if (lane == 0) { ss[warp] = s; sr[warp] = r0; sc[warp] = c0; }
        __syncthreads();

        if (warp == 0) {
            float fs = (lane < 8) ? ss[lane] : 0.f;
            float fr = (lane < 8) ? sr[lane] : 0.f;
            float fc = (lane < 8) ? sc[lane] : 0.f;
            #pragma unroll
            for (int off = 4; off > 0; off >>= 1) {
                fs += __shfl_xor_sync(0xFFFFFFFFu, fs, off);
                fr += __shfl_xor_sync(0xFFFFFFFFu, fr, off);
                fc += __shfl_xor_sync(0xFFFFFFFFu, fc, off);
            }
            if (lane == 0) {
                const int b = bc >> 8;
                const int c = bc & 255;
                g_statsT[c * B_ + b] = make_float4(fs, fr, fc, sv00);
            }
        }
    } else {
        const int i = (blockIdx.x - BC_) * 256 + threadIdx.x;   // i = c*256 + o
        const int c = i >> 8;
        const int o = i & 255;
        const float* p = w + (size_t)i * 9;
        float w00 = p[0], w01 = p[1], w02 = p[2];
        float w10 = p[3], w11 = p[4], w12 = p[5];
        float w20 = p[6], w21 = p[7], w22 = p[8];
        float wsum = ((w00 + w01) + (w02 + w10)) + ((w11 + w12) + (w20 + w21)) + w22;
        float wkh0 = w00 + w01 + w02;   // kh == 0 row
        float wkw0 = w00 + w10 + w20;   // kw == 0 col
        g_wcatT[o * C_ + c] = make_float4(wsum, -wkh0, -wkw0, w00);
    }
}

// ---------------------------------------------------------------------------
// Kernel B: MLP-maximized micro-GEMM.
// grid = (o-tile, q) = 32*16 = 512 blocks, 256 threads (warp = o, lane = b).
//   All 16 stats float4 loads are FRONT-BATCHED into a register array before
//   any FMA -> 16 independent LDG.128 in flight (cold-DRAM latency / 16
//   instead of / ~4). Weight row: one coalesced 16-lane float4 load per warp
//   into smem, issued before the barrier so it overlaps the stats fetch.
// ---------------------------------------------------------------------------
__global__ void __launch_bounds__(256) gemm_kernel(const float* __restrict__ bias,
                                                   float* __restrict__ out) {
    const int ot = blockIdx.x >> 4;        // / NQ_
    const int q  = blockIdx.x & (NQ_ - 1);
    const int t  = threadIdx.x;
    const int obase = ot * OT_;
    const int cbase = q * QC_;

    const int o_l = t >> 5;                // warp = local o
    const int b   = t & 31;                // lane = batch

    __shared__ float4 wsm[OT_][QC_];
    __shared__ unsigned int s_old;

    // weight row for this warp's o: lanes 0..15 load one float4 each
    if (b < QC_)
        wsm[o_l][b] = g_wcatT[(obase + o_l) * C_ + cbase + b];

    // FRONT-BATCHED stats loads: 16 independent LDG.128, no consumer between
    float4 a[QC_];
    #pragma unroll
    for (int k = 0; k < QC_; k++)
        a[k] = g_statsT[(cbase + k) * B_ + b];

    __syncthreads();                       // wsm visible

    float acc0 = 0.f, acc1 = 0.f;
    #pragma unroll
    for (int k = 0; k < QC_; k += 2) {
        const float4 w0 = wsm[o_l][k];
        const float4 w1 = wsm[o_l][k + 1];
        acc0 = fmaf(a[k].x, w0.x, acc0);
        acc1 = fmaf(a[k + 1].x, w1.x, acc1);
        acc0 = fmaf(a[k].y, w0.y, acc0);
        acc1 = fmaf(a[k + 1].y, w1.y, acc1);
        acc0 = fmaf(a[k].z, w0.z, acc0);
        acc1 = fmaf(a[k + 1].z, w1.z, acc1);
        acc0 = fmaf(a[k].w, w0.w, acc0);
        acc1 = fmaf(a[k + 1].w, w1.w, acc1);
    }
    g_part[ot][q][o_l][b] = acc0 + acc1;   // coalesced 128 B per warp

    // election (acq_rel orders the partial stores; no CCTL)
    __syncthreads();
    if (t == 0) s_old = acqrel_add(&g_done[ot * 32]);
    __syncthreads();

    if (s_old == (unsigned int)NQ_ - 1u) { // last block for this o-tile
        // 16 independent L2-hot loads, front-batched by unroll
        float p[NQ_];
        #pragma unroll
        for (int qq = 0; qq < NQ_; qq++)
            p[qq] = __ldcg(&g_part[ot][qq][o_l][b]);
        float sacc = 0.f;
        #pragma unroll
        for (int qq = 0; qq < NQ_; qq++)   // fixed order -> deterministic
            sacc += p[qq];
        const int o = obase + o_l;
        out[b * O_ + o] = 2.0f * (sacc * (1.0f / 16384.0f) + __ldg(&bias[o]));
        if (t == 0) atomicExch(&g_done[ot * 32], 0u);   // replay-safe reset
    }
}

// ---------------------------------------------------------------------------
extern "C" void kernel_launch(void* const* d_in, const int* in_sizes, int n_in,
                              void* d_out, int out_size) {
    const float* x    = (const float*)d_in[0];
    const float* wgt  = (const float*)d_in[1];
    const float* bias = (const float*)d_in[2];
    float* out        = (float*)d_out;

    fused_prep_kernel<<<BC_ + WPREP_BLOCKS, 256>>>(x, wgt);
    gemm_kernel<<<NOT_ * NQ_, 256>>>(bias, out);
}

// round 14
// speedup vs baseline: 1.1380x; 1.0576x over previous
#include <cuda_runtime.h>

// x: [32, 256, 64, 64] f32; weight: [256, 256, 3, 3] f32; bias: [256] f32
// out: [32, 256, 1, 1] f32   (spatial = 128*128 = 16384)
#define B_   32
#define C_   256
#define O_   256
#define HW_  4096            // 64*64
#define BC_  (B_ * C_)       // 8192 stats blocks (kernel A grid)

// Kernel-B tiling: block = (8 o's) x (16 channels), grid = 32*16 = 512
#define OT_  8
#define QC_  16
#define NOT_ (O_ / OT_)      // 32 o-tiles
#define NQ_  (C_ / QC_)      // 16 channel-tiles

// Scratch (no allocations). g_done zero-init at load; reset each launch.
__device__ float4 g_statsT[BC_];              // [c][b] -> (T, R0, C0, x00)
__device__ float  g_part[NOT_][NQ_][OT_][B_]; // partial sums
__device__ unsigned int g_done[NOT_ * 32];    // per-o-tile ctr, line-padded

// acq_rel fetch-add: releases prior stores, acquires others'; NO CCTL.IVALL
__device__ __forceinline__ unsigned int acqrel_add(unsigned int* p) {
    unsigned int v;
    asm volatile("atom.acq_rel.gpu.add.u32 %0, [%1], %2;"
                 : "=r"(v) : "l"(p), "r"(1u) : "memory");
    return v;
}

// ---------------------------------------------------------------------------
// Kernel A: pure stats stream (wprep removed — B folds weights itself).
// One block per (b,c) 16 KB image, 256 threads, 4x float4 (__ldcs).
// PDL trigger at block START: all 8448->8192 blocks trigger as they begin,
// so kernel B becomes schedulable when A's LAST WAVE starts (~2.7us early).
// ---------------------------------------------------------------------------
__global__ void __launch_bounds__(256) stats_kernel(const float* __restrict__ x) {
    cudaTriggerProgrammaticLaunchCompletion();   // early trigger: max overlap

    const int bc = blockIdx.x;
    const float4* __restrict__ p4 =
        reinterpret_cast<const float4*>(x + (size_t)bc * HW_);
    const int t = threadIdx.x;

    float s = 0.f, r0 = 0.f, c0 = 0.f, v00 = 0.f;

    #pragma unroll
    for (int i = 0; i < 4; i++) {
        const int j = t + i * 256;        // float4 index 0..1023
        float4 v = __ldcs(&p4[j]);        // streaming, read-once
        float vs = v.x + v.y + v.z + v.w;
        s += vs;
        if (j < 16)          r0 += vs;    // row 0 = first 64 elems
        if ((j & 15) == 0)   c0 += v.x;   // col 0 = elem % 64 == 0
        if (j == 0)          v00 = v.x;
    }

    #pragma unroll
    for (int off = 16; off > 0; off >>= 1) {
        s  += __shfl_xor_sync(0xFFFFFFFFu, s,  off);
        r0 += __shfl_xor_sync(0xFFFFFFFFu, r0, off);
        c0 += __shfl_xor_sync(0xFFFFFFFFu, c0, off);
    }

    __shared__ float ss[8], sr[8], sc[8];
    __shared__ float sv00;
    const int warp = t >> 5, lane = t & 31;
    if (t == 0) sv00 = v00;
    if (lane == 0) { ss[warp] = s; sr[warp] = r0; sc[warp] = c0; }
    __syncthreads();

    if (warp == 0) {
        float fs = (lane < 8) ? ss[lane] : 0.f;
        float fr = (lane < 8) ? sr[lane] : 0.f;
        float fc = (lane < 8) ? sc[lane] : 0.f;
        #pragma unroll
        for (int off = 4; off > 0; off >>= 1) {
            fs += __shfl_xor_sync(0xFFFFFFFFu, fs, off);
            fr += __shfl_xor_sync(0xFFFFFFFFu, fr, off);
            fc += __shfl_xor_sync(0xFFFFFFFFu, fc, off);
        }
        if (lane == 0) {
            const int b = bc >> 8;
            const int c = bc & 255;
            g_statsT[c * B_ + b] = make_float4(fs, fr, fc, sv00);
        }
    }
}

// ---------------------------------------------------------------------------
// Kernel B (PDL secondary): grid = (o-tile, q) = 32*16 = 512 blocks.
//   PRE-SYNC  (overlapped with A's tail): fold raw 3x3 weights for this
//             block's 128 (c,o) pairs -> smem; load bias. Touches only
//             kernel inputs — safe before the dependency resolves.
//   cudaGridDependencySynchronize(): hardware wait for A + memory flush.
//   POST-SYNC (short): 16 front-batched stats loads (L2-hot), dot4,
//             partial store, acq_rel election, fixed-order combine, epilogue.
// ---------------------------------------------------------------------------
__global__ void __launch_bounds__(256) gemm_kernel(const float* __restrict__ w,
                                                   const float* __restrict__ bias,
                                                   float* __restrict__ out) {
    const int ot = blockIdx.x >> 4;        // / NQ_
    const int q  = blockIdx.x & (NQ_ - 1);
    const int t  = threadIdx.x;
    const int obase = ot * OT_;
    const int cbase = q * QC_;

    const int o_l = t >> 5;                // warp = local o
    const int b   = t & 31;                // lane = batch

    __shared__ float4 wsm[OT_][QC_];       // [o_local][c_local]
    __shared__ float  bsm[OT_];
    __shared__ unsigned int s_old;

    // ---- PRE-SYNC: fold weights (inputs only; hidden under A's tail) ----
    if (t < QC_ * OT_) {
        const int c_l = t >> 3;            // / OT_
        const int oo  = t & (OT_ - 1);
        const float* p = w + ((size_t)(cbase + c_l) * O_ + (obase + oo)) * 9;
        float w00 = __ldg(p + 0), w01 = __ldg(p + 1), w02 = __ldg(p + 2);
        float w10 = __ldg(p + 3), w11 = __ldg(p + 4), w12 = __ldg(p + 5);
        float w20 = __ldg(p + 6), w21 = __ldg(p + 7), w22 = __ldg(p + 8);
        float wsum = ((w00 + w01) + (w02 + w10)) + ((w11 + w12) + (w20 + w21)) + w22;
        float wkh0 = w00 + w01 + w02;      // kh == 0 row
        float wkw0 = w00 + w10 + w20;      // kw == 0 col
        wsm[oo][c_l] = make_float4(wsum, -wkh0, -wkw0, w00);
    } else if (t < QC_ * OT_ + OT_) {
        const int oo = t - QC_ * OT_;
        bsm[oo] = __ldg(&bias[obase + oo]);
    }

    // ---- wait for kernel A (hardware dependency, not a spin) ----
    cudaGridDependencySynchronize();

    // ---- POST-SYNC: front-batched stats loads (16 independent LDG.128) ----
    float4 a[QC_];
    #pragma unroll
    for (int k = 0; k < QC_; k++)
        a[k] = g_statsT[(cbase + k) * B_ + b];

    __syncthreads();                       // wsm/bsm visible

    float acc0 = 0.f, acc1 = 0.f;
    #pragma unroll
    for (int k = 0; k < QC_; k += 2) {
        const float4 w0 = wsm[o_l][k];
        const float4 w1 = wsm[o_l][k + 1];
        acc0 = fmaf(a[k].x, w0.x, acc0);
        acc1 = fmaf(a[k + 1].x, w1.x, acc1);
        acc0 = fmaf(a[k].y, w0.y, acc0);
        acc1 = fmaf(a[k + 1].y, w1.y, acc1);
        acc0 = fmaf(a[k].z, w0.z, acc0);
        acc1 = fmaf(a[k + 1].z, w1.z, acc1);
        acc0 = fmaf(a[k].w, w0.w, acc0);
        acc1 = fmaf(a[k + 1].w, w1.w, acc1);
    }
    g_part[ot][q][o_l][b] = acc0 + acc1;   // coalesced 128 B per warp

    // ---- election (acq_rel orders partial stores; no CCTL) ----
    __syncthreads();
    if (t == 0) s_old = acqrel_add(&g_done[ot * 32]);
    __syncthreads();

    if (s_old == (unsigned int)NQ_ - 1u) { // last block for this o-tile
        float p[NQ_];
        #pragma unroll
        for (int qq = 0; qq < NQ_; qq++)   // front-batched L2-hot loads
            p[qq] = __ldcg(&g_part[ot][qq][o_l][b]);
        float sacc = 0.f;
        #pragma unroll
        for (int qq = 0; qq < NQ_; qq++)   // fixed order -> deterministic
            sacc += p[qq];
        const int o = obase + o_l;
        out[b * O_ + o] = 2.0f * (sacc * (1.0f / 16384.0f) + bsm[o_l]);
        if (t == 0) atomicExch(&g_done[ot * 32], 0u);   // replay-safe reset
    }
}

// ---------------------------------------------------------------------------
extern "C" void kernel_launch(void* const* d_in, const int* in_sizes, int n_in,
                              void* d_out, int out_size) {
    const float* x    = (const float*)d_in[0];
    const float* wgt  = (const float*)d_in[1];
    const float* bias = (const float*)d_in[2];
    float* out        = (float*)d_out;

    stats_kernel<<<BC_, 256>>>(x);

    // Secondary launch with Programmatic Dependent Launch: may begin while
    // the stats kernel drains; gemm_kernel gates on cudaGridDependencySynchronize.
    cudaLaunchConfig_t cfg = {};
    cfg.gridDim  = dim3(NOT_ * NQ_, 1, 1);
    cfg.blockDim = dim3(256, 1, 1);
    cfg.dynamicSmemBytes = 0;
    cudaLaunchAttribute attr[1];
    attr[0].id = cudaLaunchAttributeProgrammaticStreamSerialization;
    attr[0].val.programmaticStreamSerializationAllowed = 1;
    cfg.attrs = attr;
    cfg.numAttrs = 1;
    cudaLaunchKernelEx(&cfg, gemm_kernel, wgt, bias, out);
}